// round 6
// baseline (speedup 1.0000x reference)
#include <cuda_runtime.h>
#include <cuda_bf16.h>
#include <stdint.h>

#define NN 100000
#define NE 1600000
#define FD 128
#define NC 40

// ---------------- scratch (static device allocations are allowed) ----------
__device__ int   g_deg[NN];
__device__ int   g_start[NN];
__device__ int   g_cursor[NN];
__device__ float g_invdeg[NN];
__device__ int   g_csr[NE];
__device__ float g_hA[(size_t)NN * FD];
__device__ float g_hB[(size_t)NN * FD];
__device__ float g_agg[(size_t)NN * FD];
__device__ int   g_mask4;   // 1 if mask stored 4 bytes/elem, 0 if 1 byte/elem

// ---------------- tiny helpers --------------------------------------------
__device__ __forceinline__ const float* pick_in(int sel, const float* p) {
    if (sel == 1) return g_hA;
    if (sel == 2) return g_hB;
    return p;
}
__device__ __forceinline__ float* pick_out(int sel, float* p) {
    if (sel == 1) return g_hA;
    if (sel == 2) return g_hB;
    return p;
}

// ---------------- mask dtype detection ------------------------------------
__global__ void k_detect(const unsigned int* __restrict__ m) {
    if (threadIdx.x == 0 && blockIdx.x == 0) {
        int four = 1;
        for (int i = 0; i < 64; i++) {
            unsigned v = m[i];
            if (!(v == 0u || v == 1u || v == 0x3F800000u)) { four = 0; break; }
        }
        g_mask4 = four;
    }
}

// ---------------- CSR build ------------------------------------------------
__global__ void k_zero_deg() {
    int i = blockIdx.x * blockDim.x + threadIdx.x;
    if (i < NN) g_deg[i] = 0;
}

__global__ void k_hist(const int* __restrict__ dst) {
    int i = blockIdx.x * blockDim.x + threadIdx.x;
    if (i < NE) atomicAdd(&g_deg[dst[i]], 1);
}

__global__ void k_scan() {
    __shared__ int partial[1024];
    const int tid = threadIdx.x;
    const int chunk = (NN + 1023) / 1024;          // 98
    const int beg = tid * chunk;
    const int end = min(beg + chunk, NN);
    int s = 0;
    for (int j = beg; j < end; j++) s += g_deg[j];
    partial[tid] = s;
    __syncthreads();
    for (int off = 1; off < 1024; off <<= 1) {
        int v = (tid >= off) ? partial[tid - off] : 0;
        __syncthreads();
        partial[tid] += v;
        __syncthreads();
    }
    int run = (tid == 0) ? 0 : partial[tid - 1];
    for (int j = beg; j < end; j++) {
        int d = g_deg[j];
        g_start[j]  = run;
        g_cursor[j] = run;
        g_invdeg[j] = 1.0f / (float)(d > 0 ? d : 1);
        run += d;
    }
}

__global__ void k_scatter(const int* __restrict__ src, const int* __restrict__ dst) {
    int i = blockIdx.x * blockDim.x + threadIdx.x;
    if (i < NE) {
        int d = dst[i];
        int p = atomicAdd(&g_cursor[d], 1);
        g_csr[p] = src[i];
    }
}

// ---------------- mean aggregation (warp per node) -------------------------
__global__ void k_agg(int hsel, const float* __restrict__ hp) {
    const float* __restrict__ h = pick_in(hsel, hp);
    int gw   = (blockIdx.x * blockDim.x + threadIdx.x) >> 5;
    int lane = threadIdx.x & 31;
    if (gw >= NN) return;
    int s = g_start[gw];
    int d = g_deg[gw];
    float4 acc0 = make_float4(0.f, 0.f, 0.f, 0.f);
    float4 acc1 = make_float4(0.f, 0.f, 0.f, 0.f);
    int e = 0;
    for (; e + 1 < d; e += 2) {
        int s0 = g_csr[s + e];
        int s1 = g_csr[s + e + 1];
        float4 v0 = ((const float4*)(h + (size_t)s0 * FD))[lane];
        float4 v1 = ((const float4*)(h + (size_t)s1 * FD))[lane];
        acc0.x += v0.x; acc0.y += v0.y; acc0.z += v0.z; acc0.w += v0.w;
        acc1.x += v1.x; acc1.y += v1.y; acc1.z += v1.z; acc1.w += v1.w;
    }
    if (e < d) {
        int s0 = g_csr[s + e];
        float4 v0 = ((const float4*)(h + (size_t)s0 * FD))[lane];
        acc0.x += v0.x; acc0.y += v0.y; acc0.z += v0.z; acc0.w += v0.w;
    }
    float iv = g_invdeg[gw];
    float4 r;
    r.x = (acc0.x + acc1.x) * iv;
    r.y = (acc0.y + acc1.y) * iv;
    r.z = (acc0.z + acc1.z) * iv;
    r.w = (acc0.w + acc1.w) * iv;
    ((float4*)(g_agg + (size_t)gw * FD))[lane] = r;
}

// ---------------- fused GEMM: out = [h|agg] @ [W_self;W_neigh] + b ---------
// BM=128, BK=16, K=256 total. 256 threads, thread tile TM=8 x TN.
// EPI=1: out = relu(mask ? val : gh[g2[row]]);  EPI=0: out = val.
template<int BN, int TN, int EPI>
__global__ void __launch_bounds__(256)
k_gemm(int a0sel, const float* __restrict__ A0p,
       const float* __restrict__ B0, const float* __restrict__ B1,
       const float* __restrict__ bias,
       int osel, float* __restrict__ outp, int Nout,
       const void* __restrict__ maskp,
       const float* __restrict__ gh, const int* __restrict__ g2)
{
    constexpr int BM = 128, BK = 16, TM = 8;
    constexpr int TX = BN / TN;                 // 16
    constexpr int BLD = BK * BN / 256;          // floats per thread for B tile

    const float* __restrict__ A0 = pick_in(a0sel, A0p);
    const float* __restrict__ A1 = g_agg;
    float* __restrict__ out = pick_out(osel, outp);

    __shared__ float As[BK][BM];
    __shared__ float Bs[BK][BN];

    const int tid = threadIdx.x;
    const int tx  = tid % TX;
    const int ty  = tid / TX;
    const int row0 = blockIdx.x * BM;

    float acc[TM][TN];
    #pragma unroll
    for (int i = 0; i < TM; i++)
        #pragma unroll
        for (int j = 0; j < TN; j++) acc[i][j] = 0.f;

    const int ar = tid >> 1;            // 0..127
    const int ak = (tid & 1) * 8;       // 0 or 8
    const int bk = (tid * BLD) / BN;    // 0..15
    const int bn = (tid * BLD) % BN;

    #pragma unroll 1
    for (int kb = 0; kb < 256 / BK; ++kb) {
        const float* __restrict__ A = (kb * BK < 128) ? A0 : A1;
        const float* __restrict__ B = (kb * BK < 128) ? B0 : B1;
        const int kBase = (kb * BK) & 127;

        // stage A fragment (2 x float4)
        float4 a0, a1;
        const int grow = row0 + ar;
        if (grow < NN) {
            const float* p = A + (size_t)grow * 128 + kBase + ak;
            a0 = *(const float4*)(p);
            a1 = *(const float4*)(p + 4);
        } else {
            a0 = make_float4(0.f, 0.f, 0.f, 0.f);
            a1 = a0;
        }
        // stage B fragment
        float4 bv[BLD / 4];
        #pragma unroll
        for (int q = 0; q < BLD / 4; q++) {
            const int nn = bn + q * 4;
            if (nn < Nout)
                bv[q] = *(const float4*)(B + (size_t)(kBase + bk) * Nout + nn);
            else
                bv[q] = make_float4(0.f, 0.f, 0.f, 0.f);
        }

        __syncthreads();
        As[ak + 0][ar] = a0.x; As[ak + 1][ar] = a0.y;
        As[ak + 2][ar] = a0.z; As[ak + 3][ar] = a0.w;
        As[ak + 4][ar] = a1.x; As[ak + 5][ar] = a1.y;
        As[ak + 6][ar] = a1.z; As[ak + 7][ar] = a1.w;
        #pragma unroll
        for (int q = 0; q < BLD / 4; q++)
            *(float4*)&Bs[bk][bn + q * 4] = bv[q];
        __syncthreads();

        #pragma unroll
        for (int kk = 0; kk < BK; kk++) {
            float af[TM], bf[TN];
            *(float4*)&af[0] = *(const float4*)&As[kk][ty * TM];
            *(float4*)&af[4] = *(const float4*)&As[kk][ty * TM + 4];
            #pragma unroll
            for (int q = 0; q < TN / 4; q++)
                *(float4*)&bf[q * 4] = *(const float4*)&Bs[kk][tx * TN + q * 4];
            #pragma unroll
            for (int i = 0; i < TM; i++)
                #pragma unroll
                for (int j = 0; j < TN; j++)
                    acc[i][j] = fmaf(af[i], bf[j], acc[i][j]);
        }
    }

    // ---- epilogue ----
    const int c0 = tx * TN;
    float bfr[TN];
    #pragma unroll
    for (int j = 0; j < TN; j++)
        bfr[j] = (c0 + j < Nout) ? bias[c0 + j] : 0.f;
    const int m4 = g_mask4;

    #pragma unroll
    for (int i = 0; i < TM; i++) {
        const int r = row0 + ty * TM + i;
        if (r >= NN) continue;
        float vals[TN];
        #pragma unroll
        for (int j = 0; j < TN; j++) vals[j] = acc[i][j] + bfr[j];
        if (EPI) {
            bool mb = m4 ? (((const unsigned int*)maskp)[r] != 0u)
                         : (((const unsigned char*)maskp)[r] != 0);
            if (!mb) {
                const float* gr = gh + (size_t)g2[r] * 128 + c0;
                #pragma unroll
                for (int q = 0; q < TN / 4; q++) {
                    float4 gv = *(const float4*)(gr + q * 4);
                    vals[q * 4 + 0] = gv.x; vals[q * 4 + 1] = gv.y;
                    vals[q * 4 + 2] = gv.z; vals[q * 4 + 3] = gv.w;
                }
            }
            #pragma unroll
            for (int j = 0; j < TN; j++) vals[j] = fmaxf(vals[j], 0.f);
        }
        float* orow = out + (size_t)r * Nout + c0;
        if (c0 + TN <= Nout) {
            #pragma unroll
            for (int q = 0; q < TN / 4; q++)
                *(float4*)(orow + q * 4) = *(const float4*)&vals[q * 4];
        } else if (c0 < Nout) {
            for (int j = 0; j < TN && c0 + j < Nout; j++) orow[j] = vals[j];
        }
    }
}

// ---------------- launch ---------------------------------------------------
extern "C" void kernel_launch(void* const* d_in, const int* in_sizes, int n_in,
                              void* d_out, int out_size)
{
    const float* feat = (const float*)d_in[0];
    const float* gh   = (const float*)d_in[1];
    const float* gh2  = (const float*)d_in[2];
    const float* W1s  = (const float*)d_in[3];
    const float* W1n  = (const float*)d_in[4];
    const float* b1   = (const float*)d_in[5];
    const float* W2s  = (const float*)d_in[6];
    const float* W2n  = (const float*)d_in[7];
    const float* b2   = (const float*)d_in[8];
    const float* W3s  = (const float*)d_in[9];
    const float* W3n  = (const float*)d_in[10];
    const float* b3   = (const float*)d_in[11];
    const int*   esrc = (const int*)d_in[12];
    const int*   edst = (const int*)d_in[13];
    const int*   g2   = (const int*)d_in[14];
    const void*  mask = (const void*)d_in[15];
    float* out = (float*)d_out;

    const int TB = 256;

    // mask dtype + CSR build (reused by all 3 layers)
    k_detect<<<1, 32>>>((const unsigned int*)mask);
    k_zero_deg<<<(NN + TB - 1) / TB, TB>>>();
    k_hist<<<(NE + TB - 1) / TB, TB>>>(edst);
    k_scan<<<1, 1024>>>();
    k_scatter<<<(NE + TB - 1) / TB, TB>>>(esrc, edst);

    const int aggBlocks  = (NN * 32 + TB - 1) / TB;
    const int gemmBlocks = (NN + 127) / 128;

    // Layer 1: feat -> hA
    k_agg<<<aggBlocks, TB>>>(0, feat);
    k_gemm<128, 8, 1><<<gemmBlocks, TB>>>(0, feat, W1s, W1n, b1,
                                          1, nullptr, 128, mask, gh, g2);
    // Layer 2: hA -> hB
    k_agg<<<aggBlocks, TB>>>(1, nullptr);
    k_gemm<128, 8, 1><<<gemmBlocks, TB>>>(1, nullptr, W2s, W2n, b2,
                                          2, nullptr, 128, mask, gh2, g2);
    // Layer 3: hB -> out (N=40, tile 64)
    k_agg<<<aggBlocks, TB>>>(2, nullptr);
    k_gemm<64, 4, 0><<<gemmBlocks, TB>>>(2, nullptr, W3s, W3n, b3,
                                         0, out, NC, nullptr, nullptr, nullptr);
}

// round 8
// speedup vs baseline: 1.3173x; 1.3173x over previous
#include <cuda_runtime.h>
#include <cuda_bf16.h>
#include <stdint.h>

#define NN 100000
#define NE 1600000
#define FD 128
#define NC 40

// ---------------- scratch (static device allocations are allowed) ----------
__device__ int   g_deg[NN];
__device__ int   g_start[NN];
__device__ int   g_cursor[NN];
__device__ float g_invdeg[NN];
__device__ int   g_csr[NE];
__device__ float g_hA[(size_t)NN * FD];
__device__ float g_hB[(size_t)NN * FD];
__device__ float g_agg[(size_t)NN * FD];
__device__ int   g_mask4;            // 1 if mask stored 4 bytes/elem, else 0
__device__ int   g_blockSums[128];
__device__ int   g_blockOff[128];

// ---------------- tiny helpers --------------------------------------------
__device__ __forceinline__ const float* pick_in(int sel, const float* p) {
    if (sel == 1) return g_hA;
    if (sel == 2) return g_hB;
    return p;
}
__device__ __forceinline__ float* pick_out(int sel, float* p) {
    if (sel == 1) return g_hA;
    if (sel == 2) return g_hB;
    return p;
}

// packed f32x2 helpers (sm_103a FFMA2 path)
__device__ __forceinline__ unsigned long long pack_dup(float a) {
    unsigned long long r;
    asm("mov.b64 %0, {%1, %1};" : "=l"(r) : "f"(a));
    return r;
}
__device__ __forceinline__ void ffma2(unsigned long long& d,
                                      unsigned long long a,
                                      unsigned long long b) {
    asm("fma.rn.f32x2 %0, %1, %2, %0;" : "+l"(d) : "l"(a), "l"(b));
}
__device__ __forceinline__ float2 unpack2(unsigned long long v) {
    float2 r;
    asm("mov.b64 {%0, %1}, %2;" : "=f"(r.x), "=f"(r.y) : "l"(v));
    return r;
}

// ---------------- mask dtype detection (one warp) ---------------------------
__global__ void k_detect(const unsigned int* __restrict__ m) {
    int lane = threadIdx.x & 31;
    unsigned bad = 0;
    for (int i = lane; i < 64; i += 32) {
        unsigned v = m[i];
        if (!(v == 0u || v == 1u || v == 0x3F800000u)) bad = 1;
    }
    unsigned any = __ballot_sync(0xFFFFFFFFu, bad);
    if (lane == 0) g_mask4 = (any == 0u) ? 1 : 0;
}

// ---------------- CSR build ------------------------------------------------
__global__ void k_zero_deg() {
    int i = blockIdx.x * blockDim.x + threadIdx.x;
    if (i < NN) g_deg[i] = 0;
}

__global__ void k_hist(const int* __restrict__ dst) {
    int i = blockIdx.x * blockDim.x + threadIdx.x;
    if (i < NE) atomicAdd(&g_deg[dst[i]], 1);
}

// --- hierarchical exclusive scan of g_deg ----------------------------------
// stage A: 98 blocks x 1024 threads, per-block exclusive scan into g_start,
//          block total into g_blockSums.
__global__ void __launch_bounds__(1024) k_scanA() {
    const int tid  = threadIdx.x;
    const int lane = tid & 31;
    const int wid  = tid >> 5;
    const int i    = blockIdx.x * 1024 + tid;

    int v = (i < NN) ? g_deg[i] : 0;
    int x = v;
    #pragma unroll
    for (int off = 1; off < 32; off <<= 1) {
        int y = __shfl_up_sync(0xFFFFFFFFu, x, off);
        if (lane >= off) x += y;
    }
    __shared__ int wsum[32];
    if (lane == 31) wsum[wid] = x;
    __syncthreads();
    if (wid == 0) {
        int w = wsum[lane];
        #pragma unroll
        for (int off = 1; off < 32; off <<= 1) {
            int y = __shfl_up_sync(0xFFFFFFFFu, w, off);
            if (lane >= off) w += y;
        }
        wsum[lane] = w;
    }
    __syncthreads();
    int base = (wid > 0) ? wsum[wid - 1] : 0;
    int incl = x + base;
    if (i < NN) g_start[i] = incl - v;
    if (tid == 1023) g_blockSums[blockIdx.x] = incl;
}

// stage B: one block of 128 threads scans the (<=128) block sums.
__global__ void k_scanB(int nblk) {
    const int tid  = threadIdx.x;
    const int lane = tid & 31;
    const int wid  = tid >> 5;
    int v = (tid < nblk && tid < 128) ? g_blockSums[tid] : 0;
    int x = v;
    #pragma unroll
    for (int off = 1; off < 32; off <<= 1) {
        int y = __shfl_up_sync(0xFFFFFFFFu, x, off);
        if (lane >= off) x += y;
    }
    __shared__ int wsum[4];
    if (lane == 31) wsum[wid] = x;
    __syncthreads();
    int base = 0;
    for (int w = 0; w < wid; w++) base += wsum[w];
    g_blockOff[tid] = x + base - v;   // exclusive
}

// stage C: apply block offsets; init cursor + invdeg.
__global__ void k_scanC() {
    int i = blockIdx.x * blockDim.x + threadIdx.x;
    if (i < NN) {
        int st = g_start[i] + g_blockOff[i >> 10];
        g_start[i]  = st;
        g_cursor[i] = st;
        int d = g_deg[i];
        g_invdeg[i] = 1.0f / (float)(d > 0 ? d : 1);
    }
}

__global__ void k_scatter(const int* __restrict__ src, const int* __restrict__ dst) {
    int i = blockIdx.x * blockDim.x + threadIdx.x;
    if (i < NE) {
        int d = dst[i];
        int p = atomicAdd(&g_cursor[d], 1);
        g_csr[p] = src[i];
    }
}

// ---------------- mean aggregation (warp per node) -------------------------
__global__ void k_agg(int hsel, const float* __restrict__ hp) {
    const float* __restrict__ h = pick_in(hsel, hp);
    int gw   = (blockIdx.x * blockDim.x + threadIdx.x) >> 5;
    int lane = threadIdx.x & 31;
    if (gw >= NN) return;
    int s = g_start[gw];
    int d = g_deg[gw];
    float4 acc0 = make_float4(0.f, 0.f, 0.f, 0.f);
    float4 acc1 = make_float4(0.f, 0.f, 0.f, 0.f);
    int e = 0;
    for (; e + 1 < d; e += 2) {
        int s0 = g_csr[s + e];
        int s1 = g_csr[s + e + 1];
        float4 v0 = ((const float4*)(h + (size_t)s0 * FD))[lane];
        float4 v1 = ((const float4*)(h + (size_t)s1 * FD))[lane];
        acc0.x += v0.x; acc0.y += v0.y; acc0.z += v0.z; acc0.w += v0.w;
        acc1.x += v1.x; acc1.y += v1.y; acc1.z += v1.z; acc1.w += v1.w;
    }
    if (e < d) {
        int s0 = g_csr[s + e];
        float4 v0 = ((const float4*)(h + (size_t)s0 * FD))[lane];
        acc0.x += v0.x; acc0.y += v0.y; acc0.z += v0.z; acc0.w += v0.w;
    }
    float iv = g_invdeg[gw];
    float4 r;
    r.x = (acc0.x + acc1.x) * iv;
    r.y = (acc0.y + acc1.y) * iv;
    r.z = (acc0.z + acc1.z) * iv;
    r.w = (acc0.w + acc1.w) * iv;
    ((float4*)(g_agg + (size_t)gw * FD))[lane] = r;
}

// ---------------- fused GEMM: out = [h|agg] @ [W_self;W_neigh] + b ---------
// BM=128, BK=16, K=256 total. 256 threads, thread tile TM=8 x TN.
// Inner product uses packed fma.rn.f32x2 (FFMA2): 2 MACs per fma-pipe issue.
// EPI=1: out = relu(mask ? val : gh[g2[row]]);  EPI=0: out = val.
template<int BN, int TN, int EPI>
__global__ void __launch_bounds__(256)
k_gemm(int a0sel, const float* __restrict__ A0p,
       const float* __restrict__ B0, const float* __restrict__ B1,
       const float* __restrict__ bias,
       int osel, float* __restrict__ outp, int Nout,
       const void* __restrict__ maskp,
       const float* __restrict__ gh, const int* __restrict__ g2)
{
    constexpr int BM = 128, BK = 16, TM = 8;
    constexpr int TX = BN / TN;                 // threads along N
    constexpr int BLD = BK * BN / 256;          // floats per thread for B tile
    constexpr int TN2 = TN / 2;

    const float* __restrict__ A0 = pick_in(a0sel, A0p);
    const float* __restrict__ A1 = g_agg;
    float* __restrict__ out = pick_out(osel, outp);

    __shared__ float As[BK][BM];
    __shared__ float Bs[BK][BN];

    const int tid = threadIdx.x;
    const int tx  = tid % TX;
    const int ty  = tid / TX;
    const int row0 = blockIdx.x * BM;

    unsigned long long acc2[TM][TN2];
    #pragma unroll
    for (int i = 0; i < TM; i++)
        #pragma unroll
        for (int j = 0; j < TN2; j++) acc2[i][j] = 0ull;

    const int ar = tid >> 1;            // 0..127
    const int ak = (tid & 1) * 8;       // 0 or 8
    const int bk = (tid * BLD) / BN;    // 0..15
    const int bn = (tid * BLD) % BN;

    #pragma unroll 1
    for (int kb = 0; kb < 256 / BK; ++kb) {
        const float* __restrict__ A = (kb * BK < 128) ? A0 : A1;
        const float* __restrict__ B = (kb * BK < 128) ? B0 : B1;
        const int kBase = (kb * BK) & 127;

        // stage A fragment (2 x float4)
        float4 a0, a1;
        const int grow = row0 + ar;
        if (grow < NN) {
            const float* p = A + (size_t)grow * 128 + kBase + ak;
            a0 = *(const float4*)(p);
            a1 = *(const float4*)(p + 4);
        } else {
            a0 = make_float4(0.f, 0.f, 0.f, 0.f);
            a1 = a0;
        }
        // stage B fragment
        float4 bv[BLD / 4];
        #pragma unroll
        for (int q = 0; q < BLD / 4; q++) {
            const int nn = bn + q * 4;
            if (nn < Nout)
                bv[q] = *(const float4*)(B + (size_t)(kBase + bk) * Nout + nn);
            else
                bv[q] = make_float4(0.f, 0.f, 0.f, 0.f);
        }

        __syncthreads();
        As[ak + 0][ar] = a0.x; As[ak + 1][ar] = a0.y;
        As[ak + 2][ar] = a0.z; As[ak + 3][ar] = a0.w;
        As[ak + 4][ar] = a1.x; As[ak + 5][ar] = a1.y;
        As[ak + 6][ar] = a1.z; As[ak + 7][ar] = a1.w;
        #pragma unroll
        for (int q = 0; q < BLD / 4; q++)
            *(float4*)&Bs[bk][bn + q * 4] = bv[q];
        __syncthreads();

        #pragma unroll
        for (int kk = 0; kk < BK; kk++) {
            float af[TM];
            *(float4*)&af[0] = *(const float4*)&As[kk][ty * TM];
            *(float4*)&af[4] = *(const float4*)&As[kk][ty * TM + 4];
            unsigned long long bp[TN2];
            #pragma unroll
            for (int q = 0; q < TN2; q++)
                bp[q] = *(const unsigned long long*)&Bs[kk][tx * TN + 2 * q];
            #pragma unroll
            for (int i = 0; i < TM; i++) {
                unsigned long long ap = pack_dup(af[i]);
                #pragma unroll
                for (int j = 0; j < TN2; j++)
                    ffma2(acc2[i][j], ap, bp[j]);
            }
        }
    }

    // ---- epilogue ----
    const int c0 = tx * TN;
    float bfr[TN];
    #pragma unroll
    for (int j = 0; j < TN; j++)
        bfr[j] = (c0 + j < Nout) ? bias[c0 + j] : 0.f;
    const int m4 = g_mask4;

    #pragma unroll
    for (int i = 0; i < TM; i++) {
        const int r = row0 + ty * TM + i;
        if (r >= NN) continue;
        float vals[TN];
        #pragma unroll
        for (int j = 0; j < TN2; j++) {
            float2 v = unpack2(acc2[i][j]);
            vals[2 * j + 0] = v.x + bfr[2 * j + 0];
            vals[2 * j + 1] = v.y + bfr[2 * j + 1];
        }
        if (EPI) {
            bool mb = m4 ? (((const unsigned int*)maskp)[r] != 0u)
                         : (((const unsigned char*)maskp)[r] != 0);
            if (!mb) {
                const float* gr = gh + (size_t)g2[r] * 128 + c0;
                #pragma unroll
                for (int q = 0; q < TN / 4; q++) {
                    float4 gv = *(const float4*)(gr + q * 4);
                    vals[q * 4 + 0] = gv.x; vals[q * 4 + 1] = gv.y;
                    vals[q * 4 + 2] = gv.z; vals[q * 4 + 3] = gv.w;
                }
            }
            #pragma unroll
            for (int j = 0; j < TN; j++) vals[j] = fmaxf(vals[j], 0.f);
        }
        float* orow = out + (size_t)r * Nout + c0;
        if (c0 + TN <= Nout) {
            #pragma unroll
            for (int q = 0; q < TN / 4; q++)
                *(float4*)(orow + q * 4) = *(const float4*)&vals[q * 4];
        } else if (c0 < Nout) {
            for (int j = 0; j < TN && c0 + j < Nout; j++) orow[j] = vals[j];
        }
    }
}

// ---------------- launch ---------------------------------------------------
extern "C" void kernel_launch(void* const* d_in, const int* in_sizes, int n_in,
                              void* d_out, int out_size)
{
    const float* feat = (const float*)d_in[0];
    const float* gh   = (const float*)d_in[1];
    const float* gh2  = (const float*)d_in[2];
    const float* W1s  = (const float*)d_in[3];
    const float* W1n  = (const float*)d_in[4];
    const float* b1   = (const float*)d_in[5];
    const float* W2s  = (const float*)d_in[6];
    const float* W2n  = (const float*)d_in[7];
    const float* b2   = (const float*)d_in[8];
    const float* W3s  = (const float*)d_in[9];
    const float* W3n  = (const float*)d_in[10];
    const float* b3   = (const float*)d_in[11];
    const int*   esrc = (const int*)d_in[12];
    const int*   edst = (const int*)d_in[13];
    const int*   g2   = (const int*)d_in[14];
    const void*  mask = (const void*)d_in[15];
    float* out = (float*)d_out;

    const int TB = 256;
    const int scanBlocks = (NN + 1023) / 1024;   // 98

    // mask dtype + CSR build (reused by all 3 layers)
    k_detect<<<1, 32>>>((const unsigned int*)mask);
    k_zero_deg<<<(NN + TB - 1) / TB, TB>>>();
    k_hist<<<(NE + TB - 1) / TB, TB>>>(edst);
    k_scanA<<<scanBlocks, 1024>>>();
    k_scanB<<<1, 128>>>(scanBlocks);
    k_scanC<<<(NN + TB - 1) / TB, TB>>>();
    k_scatter<<<(NE + TB - 1) / TB, TB>>>(esrc, edst);

    const int aggBlocks  = (NN * 32 + TB - 1) / TB;
    const int gemmBlocks = (NN + 127) / 128;

    // Layer 1: feat -> hA
    k_agg<<<aggBlocks, TB>>>(0, feat);
    k_gemm<128, 8, 1><<<gemmBlocks, TB>>>(0, feat, W1s, W1n, b1,
                                          1, nullptr, 128, mask, gh, g2);
    // Layer 2: hA -> hB
    k_agg<<<aggBlocks, TB>>>(1, nullptr);
    k_gemm<128, 8, 1><<<gemmBlocks, TB>>>(1, nullptr, W2s, W2n, b2,
                                          2, nullptr, 128, mask, gh2, g2);
    // Layer 3: hB -> out (N=40, tile 64)
    k_agg<<<aggBlocks, TB>>>(2, nullptr);
    k_gemm<64, 4, 0><<<gemmBlocks, TB>>>(2, nullptr, W3s, W3n, b3,
                                         0, out, NC, nullptr, nullptr, nullptr);
}